// round 5
// baseline (speedup 1.0000x reference)
#include <cuda_runtime.h>
#include <cuda_bf16.h>
#include <cstdint>

// LogitSeparator: out[b,d,j] = logits[b, start(b,d)+j] for j < len(b,d) else 0
//                 mask[b,d,j] = (j < len) ? 1.0 : 0.0
// start = exclusive cumsum of schemas[b,:] at d; len = schemas[b,d].
// Output layout: [out (B*D*L f32)] ++ [mask (B*D*L f32)]  (verified, rel_err 0).
//
// R5 design: persistent flat kernel. Each CTA first builds the complete
// (start,len) meta table for all rows in shared memory (warp-parallel scans),
// then grid-strides over every output float4 vector. This removes the
// 3.46-wave quantization of the row-per-CTA version and keeps every SM
// feeding DRAM until the last vector. Streaming (.cs) stores avoid L2
// write-allocate churn on a 134MB output that exceeds L2 capacity.

#define D_DIM    32
#define MAX_ROWS 2048
#define NCTAS    592          // 4 CTAs/SM * 148 SMs (grid-stride: correct anyway)

__global__ void __launch_bounds__(512, 4)
flat_fill_kernel(const unsigned int* __restrict__ schemas_w,
                 const float* __restrict__ logits,
                 float* __restrict__ out,
                 int n_rows, int L) {
    __shared__ int2 s_meta[MAX_ROWS];
    __shared__ int  s_is64;

    const int tid   = threadIdx.x;
    const int lane  = tid & 31;
    const int warp  = tid >> 5;
    const int nwarp = blockDim.x >> 5;
    const int B     = n_rows / D_DIM;

    // ---- dtype detection (int64 schemas in [0,256): odd words all zero) ----
    if (warp == 0) {
        unsigned int oddw = schemas_w[2 * lane + 1];
        int is64 = (__ballot_sync(0xffffffffu, oddw != 0u) == 0u) ? 1 : 0;
        if (lane == 0) s_is64 = is64;
    }
    __syncthreads();
    const int is64 = s_is64;

    // ---- build full meta table: one warp-scan per batch row ----
    for (int b = warp; b < B; b += nwarp) {
        int idx = b * D_DIM + lane;
        int v = (int)(is64 ? schemas_w[2 * idx] : schemas_w[idx]);
        int x = v;
        #pragma unroll
        for (int o = 1; o < 32; o <<= 1) {
            int y = __shfl_up_sync(0xffffffffu, x, o);
            if (lane >= o) x += y;
        }
        s_meta[idx] = make_int2(x - v, v);   // (start, len)
    }
    __syncthreads();

    // ---- flat grid-stride over all float4 vectors of the out array ----
    const int nvec = L >> 2;                              // vectors per row
    const long long total = (long long)n_rows * nvec;
    float* __restrict__ mout = out + (long long)n_rows * L;

    const float4 z4 = make_float4(0.f, 0.f, 0.f, 0.f);
    const float4 o4 = make_float4(1.f, 1.f, 1.f, 1.f);

    const long long stride = (long long)gridDim.x * blockDim.x;
    for (long long vv = (long long)blockIdx.x * blockDim.x + tid;
         vv < total; vv += stride) {
        int row = (int)(vv / nvec);
        int v   = (int)(vv - (long long)row * nvec);
        int j   = v << 2;
        int2 m  = s_meta[row];

        long long off = (long long)row * L + j;
        float4* op = reinterpret_cast<float4*>(out  + off);
        float4* mp = reinterpret_cast<float4*>(mout + off);

        if (j >= m.y) {
            // bulk zero-fill (~98.5% of vectors)
            __stcs(op, z4);
            __stcs(mp, z4);
        } else {
            const float* __restrict__ lrow =
                logits + (long long)(row >> 5) * L + m.x;   // b = row / D_DIM
            if (j + 3 < m.y) {
                float4 val;
                val.x = lrow[j + 0];
                val.y = lrow[j + 1];
                val.z = lrow[j + 2];
                val.w = lrow[j + 3];
                __stcs(op, val);
                __stcs(mp, o4);
            } else {
                // boundary vector (at most one per row)
                float4 val = z4, mk = z4;
                if (j + 0 < m.y) { val.x = lrow[j + 0]; mk.x = 1.f; }
                if (j + 1 < m.y) { val.y = lrow[j + 1]; mk.y = 1.f; }
                if (j + 2 < m.y) { val.z = lrow[j + 2]; mk.z = 1.f; }
                __stcs(op, val);
                __stcs(mp, mk);
            }
        }
    }
}

extern "C" void kernel_launch(void* const* d_in, const int* in_sizes, int n_in,
                              void* d_out, int out_size) {
    const unsigned int* schemas_w = (const unsigned int*)d_in[0];
    const float*        logits    = (const float*)d_in[1];
    float*              out       = (float*)d_out;

    int n_rows = in_sizes[0];             // B*D = 2048
    int B      = n_rows / D_DIM;          // 64
    int L      = in_sizes[1] / B;         // 8192

    flat_fill_kernel<<<NCTAS, 512>>>(schemas_w, logits, out, n_rows, L);
}

// round 6
// speedup vs baseline: 1.0914x; 1.0914x over previous
#include <cuda_runtime.h>
#include <cuda_bf16.h>
#include <cstdint>

// LogitSeparator: out[b,d,j] = logits[b, start(b,d)+j] for j < len(b,d) else 0
//                 mask[b,d,j] = (j < len) ? 1.0 : 0.0
// start = exclusive cumsum of schemas[b,:] at d; len = schemas[b,d].
// Output layout: [out (B*D*L f32)] ++ [mask (B*D*L f32)]  (verified, rel_err 0).
//
// R6 design: ~98.5% of output bytes are 0.0f. Zero the whole 134MB output via
// one cudaMemsetAsync node (graph-capturable, runs on the near-peak fill path),
// then a tiny kernel writes only the live zone data (~4MB stores, ~1MB reads).
// Boundary float4s may store trailing zeros: memset already zeroed them and a
// zone never reaches the row's L-boundary (sum(schemas) <= 32*255 < 8192).

#define D_DIM 32

__global__ void __launch_bounds__(128)
zone_fill_kernel(const unsigned int* __restrict__ schemas_w,
                 const float* __restrict__ logits,
                 float* __restrict__ out,
                 int n_rows, int L) {
    int row = blockIdx.x;                 // b*D + d
    int b   = row >> 5;                   // D_DIM == 32
    int d   = row & (D_DIM - 1);

    __shared__ int s_start, s_len;

    if (threadIdx.x < 32) {
        int lane = threadIdx.x;
        // dtype detect: int64 schemas in [0,256) -> odd 32-bit words all zero
        unsigned int oddw = schemas_w[2 * lane + 1];
        bool is64 = (__ballot_sync(0xffffffffu, oddw != 0u) == 0u);

        int idx = b * D_DIM + lane;
        int v = (int)(is64 ? schemas_w[2 * idx] : schemas_w[idx]);
        int x = v;
        #pragma unroll
        for (int o = 1; o < 32; o <<= 1) {
            int y = __shfl_up_sync(0xffffffffu, x, o);
            if (lane >= o) x += y;
        }
        if (lane == d) { s_start = x - v; s_len = v; }
    }
    __syncthreads();

    const int start = s_start;
    const int len   = s_len;
    if (len <= 0) return;

    const float* __restrict__ lrow = logits + (long long)b * L + start;
    float4* __restrict__ orow = reinterpret_cast<float4*>(out + (long long)row * L);
    float4* __restrict__ mrow = reinterpret_cast<float4*>(
        out + (long long)n_rows * L + (long long)row * L);

    const float4 o4 = make_float4(1.f, 1.f, 1.f, 1.f);
    const int nvec = (len + 3) >> 2;      // <= 64 for len < 256

    for (int v = threadIdx.x; v < nvec; v += blockDim.x) {
        int j = v << 2;
        float4 val, mk;
        if (j + 3 < len) {
            val.x = lrow[j + 0];
            val.y = lrow[j + 1];
            val.z = lrow[j + 2];
            val.w = lrow[j + 3];
            mk = o4;
        } else {
            // last vector of the zone: pad with zeros (memset-consistent)
            val = make_float4(0.f, 0.f, 0.f, 0.f);
            mk  = val;
            if (j + 0 < len) { val.x = lrow[j + 0]; mk.x = 1.f; }
            if (j + 1 < len) { val.y = lrow[j + 1]; mk.y = 1.f; }
            if (j + 2 < len) { val.z = lrow[j + 2]; mk.z = 1.f; }
            if (j + 3 < len) { val.w = lrow[j + 3]; mk.w = 1.f; }
        }
        orow[v] = val;
        mrow[v] = mk;
    }
}

extern "C" void kernel_launch(void* const* d_in, const int* in_sizes, int n_in,
                              void* d_out, int out_size) {
    const unsigned int* schemas_w = (const unsigned int*)d_in[0];
    const float*        logits    = (const float*)d_in[1];
    float*              out       = (float*)d_out;

    int n_rows = in_sizes[0];             // B*D = 2048
    int B      = n_rows / D_DIM;          // 64
    int L      = in_sizes[1] / B;         // 8192

    // Zero the entire output (out + mask halves) on the fast fill path.
    cudaMemsetAsync(d_out, 0, (size_t)out_size * sizeof(float), 0);

    // Write only the live zone data.
    zone_fill_kernel<<<n_rows, 128>>>(schemas_w, logits, out, n_rows, L);
}